// round 7
// baseline (speedup 1.0000x reference)
#include <cuda_runtime.h>
#include <cuda_bf16.h>
#include <math.h>
#include <stdint.h>

#define NP    16384
#define DIM   24
#define ESIG  65536
#define ERND  32768
#define KK    50          // reference keeps K+1 (self + K nearest)
#define CANDMAX 64

#define MT    128         // rows per CTA (8 warps x 16)
#define NT    128         // cols per staged tile
#define JG    8           // col groups
#define JT_PER ((NP/NT)/JG)   // 16 col tiles per CTA

#define SIG_BLKS   (ESIG/(256*4))        // 64
#define RND_BLKS   (ERND/(256*4))        // 32
#define EDGE_BLKS  (SIG_BLKS + RND_BLKS) // 96
#define SCAN_BLKS  ((NP/MT)*JG)          // 1024
#define MEGA_BLKS  (EDGE_BLKS + SCAN_BLKS)

// ---------------- device state ----------------
__device__ double g_acc[3];                 // [0]=signal, [1]=knn, [2]=rand
__device__ int    g_done;
__device__ int    g_maxsq = 0;              // float bits of max sq; atomicMax is idempotent per input
__device__ float  g_sq[NP];
__device__ float2 g_sqn[NP];                // {0.5*sq, norm}
__device__ int    g_pid[NP];
__device__ int    g_ccnt[NP];
__device__ int    g_cidx[NP][CANDMAX];
__device__ uint32_t g_f8w[NP][8];           // e4m3 rows (32B), PERMUTED [w0,w4,w1,w5,w2,w6,w3,w7]

// ---------------- helpers ----------------
__device__ __forceinline__ long long ldidx(const void* p, long long i, int is64) {
    if (is64) return ((const long long*)p)[i];
    return (long long)((const int*)p)[i];
}
__device__ __forceinline__ int detect64(const void* p, long long lim) {
    const long long* q = (const long long*)p;
    for (int i = 0; i < 32; i++) {
        long long v = q[i];
        if (v < 0 || v >= lim) return 0;
    }
    return 1;
}
template <int BS>
__device__ __forceinline__ void block_accum(double v, double* target) {
    __shared__ double s[BS];
    int t = threadIdx.x;
    s[t] = v;
    __syncthreads();
    for (int o = BS / 2; o > 0; o >>= 1) {
        if (t < o) s[t] += s[t + o];
        __syncthreads();
    }
    if (t == 0 && s[0] != 0.0) atomicAdd(target, s[0]);
}
__device__ __forceinline__ uint32_t smem_u32(const void* p) {
    uint32_t a;
    asm("{ .reg .u64 t; cvta.to.shared.u64 t, %1; cvt.u32.u64 %0, t; }" : "=r"(a) : "l"(p));
    return a;
}
__device__ __forceinline__ void cpa16(uint32_t s, const void* g) {
    asm volatile("cp.async.cg.shared.global [%0], [%1], 16;" :: "r"(s), "l"(g));
}
#define CPA_COMMIT() asm volatile("cp.async.commit_group;" ::: "memory")
#define CPA_WAIT0()  asm volatile("cp.async.wait_group 0;" ::: "memory")

// fp8 e4m3 m16n8k32 mma: D = A*B + C (fp32 accum), ONE instruction per K=32
__device__ __forceinline__ void mma_fp8(float* d, const uint32_t* a, uint32_t b0, uint32_t b1) {
    asm volatile(
        "mma.sync.aligned.m16n8k32.row.col.f32.e4m3.e4m3.f32 "
        "{%0,%1,%2,%3}, {%4,%5,%6,%7}, {%8,%9}, {%0,%1,%2,%3};"
        : "+f"(d[0]), "+f"(d[1]), "+f"(d[2]), "+f"(d[3])
        : "r"(a[0]), "r"(a[1]), "r"(a[2]), "r"(a[3]), "r"(b0), "r"(b1));
}

// pack 4 floats into one e4m3x4 word (little-endian byte k = val k)
__device__ __forceinline__ uint32_t cvt4_e4m3(float v0, float v1, float v2, float v3) {
    uint16_t lo, hi;
    asm("cvt.rn.satfinite.e4m3x2.f32 %0, %1, %2;" : "=h"(lo) : "f"(v1), "f"(v0));
    asm("cvt.rn.satfinite.e4m3x2.f32 %0, %1, %2;" : "=h"(hi) : "f"(v3), "f"(v2));
    return (uint32_t)lo | ((uint32_t)hi << 16);
}

__device__ __forceinline__ float edge_d2(const float* __restrict__ emb,
                                         long long a, long long b) {
    const float4* pa = (const float4*)(emb + a * DIM);  // 96B rows: 16B aligned
    const float4* pb = (const float4*)(emb + b * DIM);
    float s = 0.f;
    #pragma unroll
    for (int q = 0; q < DIM / 4; q++) {
        float4 x = pa[q], y = pb[q];
        float d0 = x.x - y.x, d1 = x.y - y.y, d2 = x.z - y.z, d3 = x.w - y.w;
        s = fmaf(d0, d0, s); s = fmaf(d1, d1, s);
        s = fmaf(d2, d2, s); s = fmaf(d3, d3, s);
    }
    return s;
}

// ---------------- prep ----------------
__global__ void k_prep(const float* __restrict__ emb, const void* __restrict__ pid) {
    __shared__ int s_is64;
    if (threadIdx.x == 0) s_is64 = detect64(pid, 1LL << 31);
    if (blockIdx.x == 0 && threadIdx.x == 0) {
        g_acc[0] = 0.0; g_acc[1] = 0.0; g_acc[2] = 0.0;
        g_done = 0;
    }
    __syncthreads();
    int i = blockIdx.x * blockDim.x + threadIdx.x;
    if (i < NP) {
        float v[32];
        float s = 0.f;
        #pragma unroll
        for (int k = 0; k < DIM; k++) {
            v[k] = emb[i * DIM + k];
            s = fmaf(v[k], v[k], s);
        }
        #pragma unroll
        for (int k = DIM; k < 32; k++) v[k] = 0.f;
        g_sq[i]   = s;
        g_sqn[i]  = make_float2(0.5f * s, sqrtf(s));
        g_pid[i]  = (int)ldidx(pid, i, s_is64);
        g_ccnt[i] = 0;
        atomicMax(&g_maxsq, __float_as_int(s));   // s >= 0: int-bit order == float order
        uint32_t w[8];
        #pragma unroll
        for (int j = 0; j < 8; j++)
            w[j] = cvt4_e4m3(v[4 * j], v[4 * j + 1], v[4 * j + 2], v[4 * j + 3]);
        uint32_t* dst = g_f8w[i];
        #pragma unroll
        for (int j = 0; j < 4; j++) { dst[2 * j] = w[j]; dst[2 * j + 1] = w[j + 4]; }
    }
}

// ---------------- mega kernel: edges + fp8 scan ----------------
__global__ void __launch_bounds__(256) k_mega(const float* __restrict__ emb,
                                              const void* __restrict__ sig,
                                              const void* __restrict__ rnd) {
    int bx = blockIdx.x;
    int t  = threadIdx.x;

    if (bx < EDGE_BLKS) {
        __shared__ int s_is64;
        if (bx < SIG_BLKS) {
            if (t == 0) s_is64 = detect64(sig, (long long)NP);
            __syncthreads();
            int base = bx * 256 * 4 + t * 4;
            int is64 = s_is64;
            float s = 0.f;
            #pragma unroll
            for (int e = 0; e < 4; e++) {
                long long a = ldidx(sig, base + e, is64);
                long long b = ldidx(sig, (long long)ESIG + base + e, is64);
                s += edge_d2(emb, a, b) + 1e-12f;
            }
            block_accum<256>((double)s, &g_acc[0]);
        } else {
            if (t == 0) s_is64 = detect64(rnd, (long long)NP);
            __syncthreads();
            int base = (bx - SIG_BLKS) * 256 * 4 + t * 4;
            int is64 = s_is64;
            float s = 0.f;
            #pragma unroll
            for (int e = 0; e < 4; e++) {
                long long a = ldidx(rnd, base + e, is64);
                long long b = ldidx(rnd, (long long)ERND + base + e, is64);
                if (g_pid[a] != g_pid[b]) {
                    float dd = sqrtf(edge_d2(emb, a, b) + 1e-12f);
                    if (dd < 1.0f) {
                        float h = 1.0f - dd;
                        s += h * h;
                    }
                }
            }
            block_accum<256>((double)s, &g_acc[2]);
        }
        return;
    }

    // ---- fp8 scan ----
    __shared__ __align__(16) uint32_t sA[MT * 8];        // 4 KB (32B rows, stride-8: conflict-free)
    __shared__ __align__(16) uint32_t sB[2][NT * 8];     // 8 KB double-buffered
    __shared__ __align__(16) float2   sbn[2][NT];        // {0.5*sq, norm} per col

    int sbx    = bx - EDGE_BLKS;
    int rowblk = sbx & (NP / MT - 1);
    int cgrp   = sbx >> 7;
    int wid  = t >> 5;
    int lane = t & 31;
    int g    = lane >> 2;
    int tig  = lane & 3;

    // stage A (1 chunk/thread) + B tile 0 + sbn[0]
    {
        int row = t >> 1, i = t & 1;
        cpa16(smem_u32(&sA[row * 8 + i * 4]), &g_f8w[rowblk * MT + row][i * 4]);
        int cbase0 = cgrp * JT_PER * NT;
        cpa16(smem_u32(&sB[0][row * 8 + i * 4]), &g_f8w[cbase0 + row][i * 4]);
        if (t < NT / 2) cpa16(smem_u32(&sbn[0][t * 2]), &g_sqn[cbase0 + t * 2]);
        CPA_COMMIT();
        CPA_WAIT0();
    }
    __syncthreads();

    // A fragments (one k32 step): LDS.64 pairs from permuted layout
    int sbase = wid * 16;
    uint32_t afr[4];
    {
        uint2 p0 = *(const uint2*)&sA[(sbase + g) * 8 + 2 * tig];      // (a0, a2)
        uint2 p1 = *(const uint2*)&sA[(sbase + g + 8) * 8 + 2 * tig];  // (a1, a3)
        afr[0] = p0.x; afr[2] = p0.y;
        afr[1] = p1.x; afr[3] = p1.y;
    }
    int rowg0 = rowblk * MT + sbase + g;
    int rowg1 = rowg0 + 8;
    float2 sn0 = g_sqn[rowg0], sn1 = g_sqn[rowg1];
    float maxn = sqrtf(__int_as_float(g_maxsq));
    // tight per-pair: push iff dot > thr_i + 0.5*sq_j - en_i*n_j   (d2_fp8 < 1.06 + 0.3 n_i n_j)
    float thr0 = sn0.x - 0.53f, en0 = 0.15f * sn0.y;
    float thr1 = sn1.x - 0.53f, en1 = 0.15f * sn1.y;
    // conservative prescreen constant (per-row margin with n_max)
    float thrpre = fminf(thr0 - en0 * maxn, thr1 - en1 * maxn) - 0.02f;

    for (int jt = 0; jt < JT_PER; jt++) {
        int buf = jt & 1;
        int cbase = (cgrp * JT_PER + jt) * NT;

        if (jt + 1 < JT_PER) {       // prefetch next tile
            int cb1 = cbase + NT;
            int nb  = buf ^ 1;
            int row = t >> 1, i = t & 1;
            cpa16(smem_u32(&sB[nb][row * 8 + i * 4]), &g_f8w[cb1 + row][i * 4]);
            if (t < NT / 2) cpa16(smem_u32(&sbn[nb][t * 2]), &g_sqn[cb1 + t * 2]);
            CPA_COMMIT();
        }

        const uint32_t* B  = sB[buf];
        const float2*   SN = sbn[buf];
        #pragma unroll 8
        for (int nb = 0; nb < NT / 8; nb++) {
            int cb = nb * 8;
            uint2 bf = *(const uint2*)&B[(cb + g) * 8 + 2 * tig];   // (b0, b1)

            float d[4] = {0.f, 0.f, 0.f, 0.f};
            mma_fp8(d, afr, bf.x, bf.y);

            int c0 = cb + tig * 2;
            float4 q = *(const float4*)&SN[c0];   // (sb_x, n_x, sb_y, n_y)
            float dmax = fmaxf(fmaxf(d[0], d[1]), fmaxf(d[2], d[3]));
            if (dmax > thrpre + fminf(q.x, q.z)) {             // rare
                if (d[0] > fmaf(-en0, q.y, thr0 + q.x)) {
                    int p = atomicAdd(&g_ccnt[rowg0], 1);
                    if (p < CANDMAX) g_cidx[rowg0][p] = cbase + c0;
                }
                if (d[1] > fmaf(-en0, q.w, thr0 + q.z)) {
                    int p = atomicAdd(&g_ccnt[rowg0], 1);
                    if (p < CANDMAX) g_cidx[rowg0][p] = cbase + c0 + 1;
                }
                if (d[2] > fmaf(-en1, q.y, thr1 + q.x)) {
                    int p = atomicAdd(&g_ccnt[rowg1], 1);
                    if (p < CANDMAX) g_cidx[rowg1][p] = cbase + c0;
                }
                if (d[3] > fmaf(-en1, q.w, thr1 + q.z)) {
                    int p = atomicAdd(&g_ccnt[rowg1], 1);
                    if (p < CANDMAX) g_cidx[rowg1][p] = cbase + c0 + 1;
                }
            }
        }
        CPA_WAIT0();
        __syncthreads();
    }
}

// ---------------- finalize: fast-path + exact recompute + hinge + finish ----------------
__global__ void k_finalize(const float* __restrict__ emb, float* out) {
    int row = blockIdx.x * blockDim.x + threadIdx.x;
    double local = 0.0;
    int nc = (row < NP) ? g_ccnt[row] : 0;
    if (nc > CANDMAX) nc = CANDMAX;
    if (nc > 1) {      // nc==1 => only self (always pushed) => contributes 0
        float cd2[CANDMAX];
        int   cidx[CANDMAX];
        float sqr = g_sq[row];
        const float4* pr = (const float4*)(emb + (long long)row * DIM);
        float4 r4[DIM / 4];
        #pragma unroll
        for (int q = 0; q < DIM / 4; q++) r4[q] = pr[q];
        for (int qq = 0; qq < nc; qq++) {
            int j = g_cidx[row][qq];
            const float4* pc = (const float4*)(emb + (long long)j * DIM);
            float dot = 0.f;
            #pragma unroll
            for (int q = 0; q < DIM / 4; q++) {
                float4 y = pc[q];
                dot = fmaf(r4[q].x, y.x, dot); dot = fmaf(r4[q].y, y.y, dot);
                dot = fmaf(r4[q].z, y.z, dot); dot = fmaf(r4[q].w, y.w, dot);
            }
            cd2[qq]  = sqr + g_sq[j] - 2.0f * dot;   // exact fp32, reference formula
            cidx[qq] = j;
        }
        for (int i = 1; i < nc; i++) {               // ascending (d2, idx)
            float dv = cd2[i]; int iv = cidx[i];
            int j = i - 1;
            while (j >= 0 && (cd2[j] > dv || (cd2[j] == dv && cidx[j] > iv))) {
                cd2[j + 1] = cd2[j]; cidx[j + 1] = cidx[j]; j--;
            }
            cd2[j + 1] = dv; cidx[j + 1] = iv;
        }
        int mypid = g_pid[row];
        int lim = nc < (KK + 1) ? nc : (KK + 1);
        for (int q = 0; q < lim; q++) {
            int j = cidx[q];
            if (j != row && g_pid[j] != mypid) {
                float d = sqrtf(fmaxf(cd2[q], 0.0f) + 1e-12f);
                if (d < 1.0f) {
                    float h = 1.0f - d;
                    local += (double)(h * h);
                }
            }
        }
    }
    block_accum<128>(local, &g_acc[1]);

    if (threadIdx.x == 0) {
        __threadfence();
        int done = atomicAdd(&g_done, 1);
        if (done == (int)gridDim.x - 1) {
            out[0] = (float)(g_acc[0] / (double)ESIG +
                             g_acc[1] / (double)NP +
                             g_acc[2] / (double)ERND);
        }
    }
}

// ---------------- launch ----------------
extern "C" void kernel_launch(void* const* d_in, const int* in_sizes, int n_in,
                              void* d_out, int out_size) {
    const float* emb = (const float*)d_in[0];
    const void*  sig = d_in[1];
    const void*  rnd = d_in[2];
    const void*  pid = d_in[3];
    float* out = (float*)d_out;

    k_prep<<<(NP + 255) / 256, 256>>>(emb, pid);
    k_mega<<<MEGA_BLKS, 256>>>(emb, sig, rnd);
    k_finalize<<<NP / 128, 128>>>(emb, out);
}

// round 9
// speedup vs baseline: 1.6172x; 1.6172x over previous
#include <cuda_runtime.h>
#include <cuda_bf16.h>
#include <math.h>
#include <stdint.h>

#define NP    16384
#define DIM   24
#define ESIG  65536
#define ERND  32768
#define KK    50          // reference keeps K+1 (self + K nearest)
#define CANDMAX 64
#define D2_SLACK 8.0f     // bf16 threshold (true cutoff 1.0; error bound ~1.2)

#define MT     128        // tile rows
#define NTILES (NP/MT)    // 128
#define NTRI   (NTILES*(NTILES+1)/2)   // 8256 triangular tile pairs
#define AROW_W 24         // smem row stride in words: LDS.64 frags conflict-free

#define SIG_BLKS   (ESIG/(256*4))        // 64
#define RND_BLKS   (ERND/(256*4))        // 32
#define EDGE_BLKS  (SIG_BLKS + RND_BLKS) // 96
#define MEGA_BLKS  (EDGE_BLKS + NTRI)

// ---------------- device state ----------------
__device__ double g_acc[3];                 // [0]=signal, [1]=knn, [2]=rand
__device__ int    g_done;
__device__ float  g_sq[NP];
__device__ float  g_sqh[NP];                // 0.5 * sq
__device__ int    g_pid[NP];
__device__ int    g_ccnt[NP];
__device__ int    g_cidx[NP][CANDMAX];
__device__ uint32_t g_bfw[NP][16];          // bf16x2 words, PERMUTED [w0,w4,w1,w5,...]

// ---------------- helpers ----------------
__device__ __forceinline__ long long ldidx(const void* p, long long i, int is64) {
    if (is64) return ((const long long*)p)[i];
    return (long long)((const int*)p)[i];
}
__device__ __forceinline__ int detect64(const void* p, long long lim) {
    const long long* q = (const long long*)p;
    for (int i = 0; i < 32; i++) {
        long long v = q[i];
        if (v < 0 || v >= lim) return 0;
    }
    return 1;
}
template <int BS>
__device__ __forceinline__ void block_accum(double v, double* target) {
    __shared__ double s[BS];
    int t = threadIdx.x;
    s[t] = v;
    __syncthreads();
    for (int o = BS / 2; o > 0; o >>= 1) {
        if (t < o) s[t] += s[t + o];
        __syncthreads();
    }
    if (t == 0 && s[0] != 0.0) atomicAdd(target, s[0]);
}
__device__ __forceinline__ uint32_t smem_u32(const void* p) {
    uint32_t a;
    asm("{ .reg .u64 t; cvta.to.shared.u64 t, %1; cvt.u32.u64 %0, t; }" : "=r"(a) : "l"(p));
    return a;
}
__device__ __forceinline__ void cpa16(uint32_t s, const void* g) {
    asm volatile("cp.async.cg.shared.global [%0], [%1], 16;" :: "r"(s), "l"(g));
}
#define CPA_COMMIT() asm volatile("cp.async.commit_group;" ::: "memory")
#define CPA_WAIT0()  asm volatile("cp.async.wait_group 0;" ::: "memory")

// bf16 m16n8k16 mma: D = A*B + C (fp32 accum)
__device__ __forceinline__ void mma16816(float* d, const uint32_t* a, const uint32_t* b) {
    asm volatile(
        "mma.sync.aligned.m16n8k16.row.col.f32.bf16.bf16.f32 "
        "{%0,%1,%2,%3}, {%4,%5,%6,%7}, {%8,%9}, {%0,%1,%2,%3};"
        : "+f"(d[0]), "+f"(d[1]), "+f"(d[2]), "+f"(d[3])
        : "r"(a[0]), "r"(a[1]), "r"(a[2]), "r"(a[3]), "r"(b[0]), "r"(b[1]));
}

__device__ __forceinline__ float edge_d2(const float* __restrict__ emb,
                                         long long a, long long b) {
    const float4* pa = (const float4*)(emb + a * DIM);  // 96B rows: 16B aligned
    const float4* pb = (const float4*)(emb + b * DIM);
    float s = 0.f;
    #pragma unroll
    for (int q = 0; q < DIM / 4; q++) {
        float4 x = pa[q], y = pb[q];
        float d0 = x.x - y.x, d1 = x.y - y.y, d2 = x.z - y.z, d3 = x.w - y.w;
        s = fmaf(d0, d0, s); s = fmaf(d1, d1, s);
        s = fmaf(d2, d2, s); s = fmaf(d3, d3, s);
    }
    return s;
}

// ---------------- prep ----------------
__global__ void k_prep(const float* __restrict__ emb, const void* __restrict__ pid) {
    __shared__ int s_is64;
    if (threadIdx.x == 0) s_is64 = detect64(pid, 1LL << 31);
    if (blockIdx.x == 0 && threadIdx.x == 0) {
        g_acc[0] = 0.0; g_acc[1] = 0.0; g_acc[2] = 0.0;
        g_done = 0;
    }
    __syncthreads();
    int i = blockIdx.x * blockDim.x + threadIdx.x;
    if (i < NP) {
        float v[32];
        float s = 0.f;
        #pragma unroll
        for (int k = 0; k < DIM; k++) {
            v[k] = emb[i * DIM + k];
            s = fmaf(v[k], v[k], s);
        }
        #pragma unroll
        for (int k = DIM; k < 32; k++) v[k] = 0.f;
        g_sq[i]   = s;
        g_sqh[i]  = 0.5f * s;
        g_pid[i]  = (int)ldidx(pid, i, s_is64);
        g_ccnt[i] = 0;
        uint32_t w[16];
        #pragma unroll
        for (int j = 0; j < 16; j++) {
            __nv_bfloat162 p = __floats2bfloat162_rn(v[2 * j], v[2 * j + 1]);
            w[j] = *(uint32_t*)&p;
        }
        uint32_t* dst = g_bfw[i];
        #pragma unroll
        for (int j = 0; j < 4; j++) { dst[2 * j] = w[j]; dst[2 * j + 1] = w[j + 4]; }
        #pragma unroll
        for (int j = 0; j < 4; j++) { dst[8 + 2 * j] = w[8 + j]; dst[9 + 2 * j] = w[12 + j]; }
    }
}

// ---------------- mega kernel: edges + symmetric triangular scan ----------------
__global__ void __launch_bounds__(256) k_mega(const float* __restrict__ emb,
                                              const void* __restrict__ sig,
                                              const void* __restrict__ rnd) {
    int bx = blockIdx.x;
    int t  = threadIdx.x;

    if (bx < EDGE_BLKS) {
        __shared__ int s_is64;
        if (bx < SIG_BLKS) {
            if (t == 0) s_is64 = detect64(sig, (long long)NP);
            __syncthreads();
            int base = bx * 256 * 4 + t * 4;
            int is64 = s_is64;
            float s = 0.f;
            #pragma unroll
            for (int e = 0; e < 4; e++) {
                long long a = ldidx(sig, base + e, is64);
                long long b = ldidx(sig, (long long)ESIG + base + e, is64);
                s += edge_d2(emb, a, b) + 1e-12f;
            }
            block_accum<256>((double)s, &g_acc[0]);
        } else {
            if (t == 0) s_is64 = detect64(rnd, (long long)NP);
            __syncthreads();
            int base = (bx - SIG_BLKS) * 256 * 4 + t * 4;
            int is64 = s_is64;
            float s = 0.f;
            #pragma unroll
            for (int e = 0; e < 4; e++) {
                long long a = ldidx(rnd, base + e, is64);
                long long b = ldidx(rnd, (long long)ERND + base + e, is64);
                if (g_pid[a] != g_pid[b]) {
                    float dd = sqrtf(edge_d2(emb, a, b) + 1e-12f);
                    if (dd < 1.0f) {
                        float h = 1.0f - dd;
                        s += h * h;
                    }
                }
            }
            block_accum<256>((double)s, &g_acc[2]);
        }
        return;
    }

    // ---- symmetric scan: one triangular tile pair (ti <= tj) per CTA ----
    __shared__ uint32_t sA[MT * AROW_W];   // 12 KB
    __shared__ uint32_t sB[MT * AROW_W];   // 12 KB
    __shared__ float    sbh[MT];           // 0.5*sq of B rows

    int b = bx - EDGE_BLKS;
    // decode triangular (ti, tj), ti <= tj; offset(ti) = ti*NTILES - ti*(ti-1)/2
    int ti = (int)(128.5f - sqrtf(fmaf(-2.0f, (float)b, 128.5f * 128.5f)));
    while ((ti + 1) * NTILES - ((ti + 1) * ti) / 2 <= b) ti++;
    while (ti * NTILES - (ti * (ti - 1)) / 2 > b) ti--;
    int tj = ti + (b - (ti * NTILES - (ti * (ti - 1)) / 2));
    bool offdiag = (ti != tj);

    int wid  = t >> 5;
    int lane = t & 31;
    int g    = lane >> 2;
    int tig  = lane & 3;

    // stage A (rows) + B (cols) + sbh
    {
        #pragma unroll
        for (int c = t; c < MT * 4; c += 256) {
            int row = c >> 2, i = c & 3;
            cpa16(smem_u32(&sA[row * AROW_W + i * 4]), &g_bfw[ti * MT + row][i * 4]);
            cpa16(smem_u32(&sB[row * AROW_W + i * 4]), &g_bfw[tj * MT + row][i * 4]);
        }
        if (t < MT / 4) cpa16(smem_u32(&sbh[t * 4]), &g_sqh[tj * MT + t * 4]);
        CPA_COMMIT();
        CPA_WAIT0();
    }
    __syncthreads();

    // A fragments for this warp's 16-row strip (LDS.64 pairs, permuted layout)
    int sbase = wid * 16;
    uint32_t afr[2][4];
    {
        int r0 = (sbase + g) * AROW_W;
        int r1 = (sbase + g + 8) * AROW_W;
        uint2 p;
        p = *(const uint2*)&sA[r0 + 2 * tig];     afr[0][0] = p.x; afr[0][2] = p.y;
        p = *(const uint2*)&sA[r1 + 2 * tig];     afr[0][1] = p.x; afr[0][3] = p.y;
        p = *(const uint2*)&sA[r0 + 8 + 2 * tig]; afr[1][0] = p.x; afr[1][2] = p.y;
        p = *(const uint2*)&sA[r1 + 8 + 2 * tig]; afr[1][1] = p.x; afr[1][3] = p.y;
    }
    int rowg0 = ti * MT + sbase + g;
    int rowg1 = rowg0 + 8;
    int cbase = tj * MT;
    float thr0 = 0.5f * (g_sq[rowg0] - D2_SLACK);   // dot > thr + 0.5*sq_col <=> d2 < slack
    float thr1 = 0.5f * (g_sq[rowg1] - D2_SLACK);
    float thrmin = fminf(thr0, thr1);

    #pragma unroll 4
    for (int nb = 0; nb < MT / 8; nb++) {
        int cb = nb * 8;
        int bq = (cb + g) * AROW_W + 2 * tig;
        uint2 b0 = *(const uint2*)&sB[bq];        // k-step 0
        uint2 b1 = *(const uint2*)&sB[bq + 8];    // k-step 1

        float d[4] = {0.f, 0.f, 0.f, 0.f};
        uint32_t bf0[2] = {b0.x, b0.y};
        uint32_t bf1[2] = {b1.x, b1.y};
        mma16816(d, afr[0], bf0);
        mma16816(d, afr[1], bf1);

        int c0 = cb + tig * 2;
        float2 sb2 = *(const float2*)&sbh[c0];
        float dmax = fmaxf(fmaxf(d[0], d[1]), fmaxf(d[2], d[3]));
        if (dmax > thrmin + fminf(sb2.x, sb2.y)) {       // rare
            // d2 < SLACK is symmetric: push both directions on off-diagonal tiles
            if (d[0] > thr0 + sb2.x) {
                int jg = cbase + c0;
                int p = atomicAdd(&g_ccnt[rowg0], 1);
                if (p < CANDMAX) g_cidx[rowg0][p] = jg;
                if (offdiag) {
                    int q = atomicAdd(&g_ccnt[jg], 1);
                    if (q < CANDMAX) g_cidx[jg][q] = rowg0;
                }
            }
            if (d[1] > thr0 + sb2.y) {
                int jg = cbase + c0 + 1;
                int p = atomicAdd(&g_ccnt[rowg0], 1);
                if (p < CANDMAX) g_cidx[rowg0][p] = jg;
                if (offdiag) {
                    int q = atomicAdd(&g_ccnt[jg], 1);
                    if (q < CANDMAX) g_cidx[jg][q] = rowg0;
                }
            }
            if (d[2] > thr1 + sb2.x) {
                int jg = cbase + c0;
                int p = atomicAdd(&g_ccnt[rowg1], 1);
                if (p < CANDMAX) g_cidx[rowg1][p] = jg;
                if (offdiag) {
                    int q = atomicAdd(&g_ccnt[jg], 1);
                    if (q < CANDMAX) g_cidx[jg][q] = rowg1;
                }
            }
            if (d[3] > thr1 + sb2.y) {
                int jg = cbase + c0 + 1;
                int p = atomicAdd(&g_ccnt[rowg1], 1);
                if (p < CANDMAX) g_cidx[rowg1][p] = jg;
                if (offdiag) {
                    int q = atomicAdd(&g_ccnt[jg], 1);
                    if (q < CANDMAX) g_cidx[jg][q] = rowg1;
                }
            }
        }
    }
}

// ---------------- finalize: fast-path + exact recompute + hinge + finish ----------------
__global__ void k_finalize(const float* __restrict__ emb, float* out) {
    int row = blockIdx.x * blockDim.x + threadIdx.x;
    double local = 0.0;
    int nc = (row < NP) ? g_ccnt[row] : 0;
    if (nc > CANDMAX) nc = CANDMAX;
    if (nc > 1) {      // nc==1 => only self (always pushed) => contributes 0
        float cd2[CANDMAX];
        int   cidx[CANDMAX];
        float sqr = g_sq[row];
        const float4* pr = (const float4*)(emb + (long long)row * DIM);
        float4 r4[DIM / 4];
        #pragma unroll
        for (int q = 0; q < DIM / 4; q++) r4[q] = pr[q];
        for (int qq = 0; qq < nc; qq++) {
            int j = g_cidx[row][qq];
            const float4* pc = (const float4*)(emb + (long long)j * DIM);
            float dot = 0.f;
            #pragma unroll
            for (int q = 0; q < DIM / 4; q++) {
                float4 y = pc[q];
                dot = fmaf(r4[q].x, y.x, dot); dot = fmaf(r4[q].y, y.y, dot);
                dot = fmaf(r4[q].z, y.z, dot); dot = fmaf(r4[q].w, y.w, dot);
            }
            cd2[qq]  = sqr + g_sq[j] - 2.0f * dot;   // exact fp32, reference formula
            cidx[qq] = j;
        }
        for (int i = 1; i < nc; i++) {               // ascending (d2, idx)
            float dv = cd2[i]; int iv = cidx[i];
            int j = i - 1;
            while (j >= 0 && (cd2[j] > dv || (cd2[j] == dv && cidx[j] > iv))) {
                cd2[j + 1] = cd2[j]; cidx[j + 1] = cidx[j]; j--;
            }
            cd2[j + 1] = dv; cidx[j + 1] = iv;
        }
        int mypid = g_pid[row];
        int lim = nc < (KK + 1) ? nc : (KK + 1);
        for (int q = 0; q < lim; q++) {
            int j = cidx[q];
            if (j != row && g_pid[j] != mypid) {
                float d = sqrtf(fmaxf(cd2[q], 0.0f) + 1e-12f);
                if (d < 1.0f) {
                    float h = 1.0f - d;
                    local += (double)(h * h);
                }
            }
        }
    }
    block_accum<128>(local, &g_acc[1]);

    if (threadIdx.x == 0) {
        __threadfence();
        int done = atomicAdd(&g_done, 1);
        if (done == (int)gridDim.x - 1) {
            out[0] = (float)(g_acc[0] / (double)ESIG +
                             g_acc[1] / (double)NP +
                             g_acc[2] / (double)ERND);
        }
    }
}

// ---------------- launch ----------------
extern "C" void kernel_launch(void* const* d_in, const int* in_sizes, int n_in,
                              void* d_out, int out_size) {
    const float* emb = (const float*)d_in[0];
    const void*  sig = d_in[1];
    const void*  rnd = d_in[2];
    const void*  pid = d_in[3];
    float* out = (float*)d_out;

    k_prep<<<(NP + 255) / 256, 256>>>(emb, pid);
    k_mega<<<MEGA_BLKS, 256>>>(emb, sig, rnd);
    k_finalize<<<NP / 128, 128>>>(emb, out);
}

// round 10
// speedup vs baseline: 1.7992x; 1.1125x over previous
#include <cuda_runtime.h>
#include <cuda_bf16.h>
#include <math.h>
#include <stdint.h>

#define NP    16384
#define DIM   24
#define ESIG  65536
#define ERND  32768
#define KK    50          // reference keeps K+1 (self + K nearest)
#define CANDMAX 64
#define D2_SLACK 8.0f     // bf16 threshold (true cutoff 1.0; error bound ~1.2)

#define MT     128        // tile rows
#define NTILES (NP/MT)    // 128
#define NTRI   (NTILES*(NTILES+1)/2)   // 8256 triangular tile pairs

#define SIG_BLKS   (ESIG/(256*4))        // 64
#define RND_BLKS   (ERND/(256*4))        // 32
#define EDGE_BLKS  (SIG_BLKS + RND_BLKS) // 96
#define MEGA_BLKS  (EDGE_BLKS + NTRI)

// ---------------- device state ----------------
__device__ double g_acc[3];                 // [0]=signal, [1]=knn, [2]=rand
__device__ int    g_done;
__device__ float  g_sq[NP];
__device__ float  g_sqh[NP];                // 0.5 * sq
__device__ int    g_pid[NP];
__device__ int    g_ccnt[NP];
__device__ int    g_cidx[NP][CANDMAX];
__device__ uint32_t g_P[NP][8];             // k16 part dims 0-15, pair layout [w0,w4,w1,w5,w2,w6,w3,w7]
__device__ uint32_t g_Q[NP][4];             // k8 part dims 16-23 [w8,w9,w10,w11]

// ---------------- helpers ----------------
__device__ __forceinline__ long long ldidx(const void* p, long long i, int is64) {
    if (is64) return ((const long long*)p)[i];
    return (long long)((const int*)p)[i];
}
__device__ __forceinline__ int detect64(const void* p, long long lim) {
    const long long* q = (const long long*)p;
    for (int i = 0; i < 32; i++) {
        long long v = q[i];
        if (v < 0 || v >= lim) return 0;
    }
    return 1;
}
template <int BS>
__device__ __forceinline__ void block_accum(double v, double* target) {
    __shared__ double s[BS];
    int t = threadIdx.x;
    s[t] = v;
    __syncthreads();
    for (int o = BS / 2; o > 0; o >>= 1) {
        if (t < o) s[t] += s[t + o];
        __syncthreads();
    }
    if (t == 0 && s[0] != 0.0) atomicAdd(target, s[0]);
}
__device__ __forceinline__ uint32_t smem_u32(const void* p) {
    uint32_t a;
    asm("{ .reg .u64 t; cvta.to.shared.u64 t, %1; cvt.u32.u64 %0, t; }" : "=r"(a) : "l"(p));
    return a;
}
__device__ __forceinline__ void cpa16(uint32_t s, const void* g) {
    asm volatile("cp.async.cg.shared.global [%0], [%1], 16;" :: "r"(s), "l"(g));
}
#define CPA_COMMIT() asm volatile("cp.async.commit_group;" ::: "memory")
#define CPA_WAIT0()  asm volatile("cp.async.wait_group 0;" ::: "memory")

// bf16 m16n8k16: D += A*B
__device__ __forceinline__ void mma16816(float* d, const uint32_t* a, uint32_t b0, uint32_t b1) {
    asm volatile(
        "mma.sync.aligned.m16n8k16.row.col.f32.bf16.bf16.f32 "
        "{%0,%1,%2,%3}, {%4,%5,%6,%7}, {%8,%9}, {%0,%1,%2,%3};"
        : "+f"(d[0]), "+f"(d[1]), "+f"(d[2]), "+f"(d[3])
        : "r"(a[0]), "r"(a[1]), "r"(a[2]), "r"(a[3]), "r"(b0), "r"(b1));
}
// bf16 m16n8k8: D += A*B (half the K work, one instruction)
__device__ __forceinline__ void mma1688(float* d, uint32_t a0, uint32_t a1, uint32_t b0) {
    asm volatile(
        "mma.sync.aligned.m16n8k8.row.col.f32.bf16.bf16.f32 "
        "{%0,%1,%2,%3}, {%4,%5}, {%6}, {%0,%1,%2,%3};"
        : "+f"(d[0]), "+f"(d[1]), "+f"(d[2]), "+f"(d[3])
        : "r"(a0), "r"(a1), "r"(b0));
}

__device__ __forceinline__ float edge_d2(const float* __restrict__ emb,
                                         long long a, long long b) {
    const float4* pa = (const float4*)(emb + a * DIM);  // 96B rows: 16B aligned
    const float4* pb = (const float4*)(emb + b * DIM);
    float s = 0.f;
    #pragma unroll
    for (int q = 0; q < DIM / 4; q++) {
        float4 x = pa[q], y = pb[q];
        float d0 = x.x - y.x, d1 = x.y - y.y, d2 = x.z - y.z, d3 = x.w - y.w;
        s = fmaf(d0, d0, s); s = fmaf(d1, d1, s);
        s = fmaf(d2, d2, s); s = fmaf(d3, d3, s);
    }
    return s;
}

__device__ __forceinline__ uint32_t bf2w(float lo, float hi) {
    __nv_bfloat162 p = __floats2bfloat162_rn(lo, hi);
    return *(uint32_t*)&p;
}

// ---------------- prep: 2 threads per point (double MLP on cold emb fetch) ----------------
__global__ void k_prep(const float* __restrict__ emb, const void* __restrict__ pid) {
    __shared__ int s_is64;
    if (threadIdx.x == 0) s_is64 = detect64(pid, 1LL << 31);
    if (blockIdx.x == 0 && threadIdx.x == 0) {
        g_acc[0] = 0.0; g_acc[1] = 0.0; g_acc[2] = 0.0;
        g_done = 0;
    }
    __syncthreads();
    int t  = threadIdx.x;
    int pt = blockIdx.x * 128 + (t >> 1);
    int h  = t & 1;
    const float4* src = (const float4*)(emb + (long long)pt * DIM);
    float s = 0.f;
    if (h == 0) {
        // dims 0-15 -> P row (pair layout)
        float4 v[4];
        #pragma unroll
        for (int q = 0; q < 4; q++) v[q] = src[q];
        float f[16];
        #pragma unroll
        for (int q = 0; q < 4; q++) {
            f[4 * q] = v[q].x; f[4 * q + 1] = v[q].y;
            f[4 * q + 2] = v[q].z; f[4 * q + 3] = v[q].w;
        }
        #pragma unroll
        for (int k = 0; k < 16; k++) s = fmaf(f[k], f[k], s);
        uint32_t w[8];   // word j = dims (2j, 2j+1); P[2j']=w_j', P[2j'+1]=w_{j'+4}
        #pragma unroll
        for (int j = 0; j < 8; j++) w[j] = bf2w(f[2 * j], f[2 * j + 1]);
        uint4* dst = (uint4*)g_P[pt];
        dst[0] = make_uint4(w[0], w[4], w[1], w[5]);
        dst[1] = make_uint4(w[2], w[6], w[3], w[7]);
    } else {
        // dims 16-23 -> Q row
        float4 v0 = src[4], v1 = src[5];
        s = fmaf(v0.x, v0.x, s); s = fmaf(v0.y, v0.y, s);
        s = fmaf(v0.z, v0.z, s); s = fmaf(v0.w, v0.w, s);
        s = fmaf(v1.x, v1.x, s); s = fmaf(v1.y, v1.y, s);
        s = fmaf(v1.z, v1.z, s); s = fmaf(v1.w, v1.w, s);
        *(uint4*)g_Q[pt] = make_uint4(bf2w(v0.x, v0.y), bf2w(v0.z, v0.w),
                                      bf2w(v1.x, v1.y), bf2w(v1.z, v1.w));
    }
    float tot = s + __shfl_xor_sync(0xffffffff, s, 1);
    if (h == 1) {
        g_sq[pt]   = tot;
        g_sqh[pt]  = 0.5f * tot;
        g_pid[pt]  = (int)ldidx(pid, pt, s_is64);
        g_ccnt[pt] = 0;
    }
}

// ---------------- mega kernel: edges + symmetric triangular scan ----------------
__global__ void __launch_bounds__(256) k_mega(const float* __restrict__ emb,
                                              const void* __restrict__ sig,
                                              const void* __restrict__ rnd) {
    int bx = blockIdx.x;
    int t  = threadIdx.x;

    if (bx < EDGE_BLKS) {
        __shared__ int s_is64;
        if (bx < SIG_BLKS) {
            if (t == 0) s_is64 = detect64(sig, (long long)NP);
            __syncthreads();
            int base = bx * 256 * 4 + t * 4;
            int is64 = s_is64;
            float s = 0.f;
            #pragma unroll
            for (int e = 0; e < 4; e++) {
                long long a = ldidx(sig, base + e, is64);
                long long b = ldidx(sig, (long long)ESIG + base + e, is64);
                s += edge_d2(emb, a, b) + 1e-12f;
            }
            block_accum<256>((double)s, &g_acc[0]);
        } else {
            if (t == 0) s_is64 = detect64(rnd, (long long)NP);
            __syncthreads();
            int base = (bx - SIG_BLKS) * 256 * 4 + t * 4;
            int is64 = s_is64;
            float s = 0.f;
            #pragma unroll
            for (int e = 0; e < 4; e++) {
                long long a = ldidx(rnd, base + e, is64);
                long long b = ldidx(rnd, (long long)ERND + base + e, is64);
                if (g_pid[a] != g_pid[b]) {
                    float dd = sqrtf(edge_d2(emb, a, b) + 1e-12f);
                    if (dd < 1.0f) {
                        float h = 1.0f - dd;
                        s += h * h;
                    }
                }
            }
            block_accum<256>((double)s, &g_acc[2]);
        }
        return;
    }

    // ---- symmetric scan: one triangular tile pair (ti <= tj) per CTA ----
    __shared__ __align__(16) uint32_t sAP[MT * 8];   // 4 KB (stride 8: LDS.64 conflict-free)
    __shared__ __align__(16) uint32_t sBP[MT * 8];   // 4 KB
    __shared__ __align__(16) uint32_t sAQ[MT * 4];   // 2 KB (stride 4: LDS.32 conflict-free)
    __shared__ __align__(16) uint32_t sBQ[MT * 4];   // 2 KB
    __shared__ __align__(16) float    sbh[MT];

    int b = bx - EDGE_BLKS;
    // decode triangular (ti, tj), ti <= tj
    int ti = (int)(128.5f - sqrtf(fmaf(-2.0f, (float)b, 128.5f * 128.5f)));
    while ((ti + 1) * NTILES - ((ti + 1) * ti) / 2 <= b) ti++;
    while (ti * NTILES - (ti * (ti - 1)) / 2 > b) ti--;
    int tj = ti + (b - (ti * NTILES - (ti * (ti - 1)) / 2));
    bool offdiag = (ti != tj);

    int wid  = t >> 5;
    int lane = t & 31;
    int g    = lane >> 2;
    int tig  = lane & 3;

    // stage: P rows (2x16B), Q rows (1x16B), sbh
    {
        int row = t >> 1, h = t & 1;
        cpa16(smem_u32(&sAP[row * 8 + h * 4]), &g_P[ti * MT + row][h * 4]);
        cpa16(smem_u32(&sBP[row * 8 + h * 4]), &g_P[tj * MT + row][h * 4]);
        if (h == 0) cpa16(smem_u32(&sAQ[row * 4]), &g_Q[ti * MT + row][0]);
        else        cpa16(smem_u32(&sBQ[row * 4]), &g_Q[tj * MT + row][0]);
        if (t < MT / 4) cpa16(smem_u32(&sbh[t * 4]), &g_sqh[tj * MT + t * 4]);
        CPA_COMMIT();
        CPA_WAIT0();
    }
    __syncthreads();

    // A fragments for this warp's 16-row strip
    int sbase = wid * 16;
    uint32_t a16[4], a8_0, a8_1;
    {
        int r0 = sbase + g, r1 = sbase + g + 8;
        uint2 p;
        p = *(const uint2*)&sAP[r0 * 8 + 2 * tig]; a16[0] = p.x; a16[2] = p.y;
        p = *(const uint2*)&sAP[r1 * 8 + 2 * tig]; a16[1] = p.x; a16[3] = p.y;
        a8_0 = sAQ[r0 * 4 + tig];
        a8_1 = sAQ[r1 * 4 + tig];
    }
    int rowg0 = ti * MT + sbase + g;
    int rowg1 = rowg0 + 8;
    int cbase = tj * MT;
    float thr0 = 0.5f * (g_sq[rowg0] - D2_SLACK);   // dot > thr + 0.5*sq_col <=> d2 < slack
    float thr1 = 0.5f * (g_sq[rowg1] - D2_SLACK);
    float thrmin = fminf(thr0, thr1);

    #pragma unroll 4
    for (int nb = 0; nb < MT / 8; nb++) {
        int cb = nb * 8;
        uint2 bp = *(const uint2*)&sBP[(cb + g) * 8 + 2 * tig];  // k16 frag
        uint32_t bq = sBQ[(cb + g) * 4 + tig];                   // k8 frag

        float d[4] = {0.f, 0.f, 0.f, 0.f};
        mma16816(d, a16, bp.x, bp.y);    // dims 0-15
        mma1688(d, a8_0, a8_1, bq);      // dims 16-23

        int c0 = cb + tig * 2;
        float2 sb2 = *(const float2*)&sbh[c0];
        float dmax = fmaxf(fmaxf(d[0], d[1]), fmaxf(d[2], d[3]));
        if (dmax > thrmin + fminf(sb2.x, sb2.y)) {       // rare
            if (d[0] > thr0 + sb2.x) {
                int jg = cbase + c0;
                int p = atomicAdd(&g_ccnt[rowg0], 1);
                if (p < CANDMAX) g_cidx[rowg0][p] = jg;
                if (offdiag) {
                    int q = atomicAdd(&g_ccnt[jg], 1);
                    if (q < CANDMAX) g_cidx[jg][q] = rowg0;
                }
            }
            if (d[1] > thr0 + sb2.y) {
                int jg = cbase + c0 + 1;
                int p = atomicAdd(&g_ccnt[rowg0], 1);
                if (p < CANDMAX) g_cidx[rowg0][p] = jg;
                if (offdiag) {
                    int q = atomicAdd(&g_ccnt[jg], 1);
                    if (q < CANDMAX) g_cidx[jg][q] = rowg0;
                }
            }
            if (d[2] > thr1 + sb2.x) {
                int jg = cbase + c0;
                int p = atomicAdd(&g_ccnt[rowg1], 1);
                if (p < CANDMAX) g_cidx[rowg1][p] = jg;
                if (offdiag) {
                    int q = atomicAdd(&g_ccnt[jg], 1);
                    if (q < CANDMAX) g_cidx[jg][q] = rowg1;
                }
            }
            if (d[3] > thr1 + sb2.y) {
                int jg = cbase + c0 + 1;
                int p = atomicAdd(&g_ccnt[rowg1], 1);
                if (p < CANDMAX) g_cidx[rowg1][p] = jg;
                if (offdiag) {
                    int q = atomicAdd(&g_ccnt[jg], 1);
                    if (q < CANDMAX) g_cidx[jg][q] = rowg1;
                }
            }
        }
    }
}

// ---------------- finalize: fast-path + exact recompute + hinge + finish ----------------
__global__ void k_finalize(const float* __restrict__ emb, float* out) {
    int row = blockIdx.x * blockDim.x + threadIdx.x;
    double local = 0.0;
    int nc = (row < NP) ? g_ccnt[row] : 0;
    if (nc > CANDMAX) nc = CANDMAX;
    if (nc > 1) {      // nc==1 => only self (always pushed) => contributes 0
        float cd2[CANDMAX];
        int   cidx[CANDMAX];
        float sqr = g_sq[row];
        const float4* pr = (const float4*)(emb + (long long)row * DIM);
        float4 r4[DIM / 4];
        #pragma unroll
        for (int q = 0; q < DIM / 4; q++) r4[q] = pr[q];
        for (int qq = 0; qq < nc; qq++) {
            int j = g_cidx[row][qq];
            const float4* pc = (const float4*)(emb + (long long)j * DIM);
            float dot = 0.f;
            #pragma unroll
            for (int q = 0; q < DIM / 4; q++) {
                float4 y = pc[q];
                dot = fmaf(r4[q].x, y.x, dot); dot = fmaf(r4[q].y, y.y, dot);
                dot = fmaf(r4[q].z, y.z, dot); dot = fmaf(r4[q].w, y.w, dot);
            }
            cd2[qq]  = sqr + g_sq[j] - 2.0f * dot;   // exact fp32, reference formula
            cidx[qq] = j;
        }
        for (int i = 1; i < nc; i++) {               // ascending (d2, idx)
            float dv = cd2[i]; int iv = cidx[i];
            int j = i - 1;
            while (j >= 0 && (cd2[j] > dv || (cd2[j] == dv && cidx[j] > iv))) {
                cd2[j + 1] = cd2[j]; cidx[j + 1] = cidx[j]; j--;
            }
            cd2[j + 1] = dv; cidx[j + 1] = iv;
        }
        int mypid = g_pid[row];
        int lim = nc < (KK + 1) ? nc : (KK + 1);
        for (int q = 0; q < lim; q++) {
            int j = cidx[q];
            if (j != row && g_pid[j] != mypid) {
                float d = sqrtf(fmaxf(cd2[q], 0.0f) + 1e-12f);
                if (d < 1.0f) {
                    float h = 1.0f - d;
                    local += (double)(h * h);
                }
            }
        }
    }
    block_accum<128>(local, &g_acc[1]);

    if (threadIdx.x == 0) {
        __threadfence();
        int done = atomicAdd(&g_done, 1);
        if (done == (int)gridDim.x - 1) {
            out[0] = (float)(g_acc[0] / (double)ESIG +
                             g_acc[1] / (double)NP +
                             g_acc[2] / (double)ERND);
        }
    }
}

// ---------------- launch ----------------
extern "C" void kernel_launch(void* const* d_in, const int* in_sizes, int n_in,
                              void* d_out, int out_size) {
    const float* emb = (const float*)d_in[0];
    const void*  sig = d_in[1];
    const void*  rnd = d_in[2];
    const void*  pid = d_in[3];
    float* out = (float*)d_out;

    k_prep<<<NP * 2 / 256, 256>>>(emb, pid);
    k_mega<<<MEGA_BLKS, 256>>>(emb, sig, rnd);
    k_finalize<<<NP / 128, 128>>>(emb, out);
}